// round 12
// baseline (speedup 1.0000x reference)
#include <cuda_runtime.h>
#include <cuda_fp16.h>
#include <cuda_bf16.h>
#include <math.h>

#define NN 50000
#define EE 800000
#define NODE_IN 128
#define HID 256
#define OUT_D 256
#define EDGE_DIM 16
#define HEADS 4
#define CH 64

#define SCAN_B 256
#define NBLK ((NN + SCAN_B - 1) / SCAN_B)   // 196

// ---------------- scratch (static device globals) ---------------------------
__device__ float   g_xcat[(size_t)NN * 512];
__device__ __half2 g_xh_h[(size_t)NN * 128];   // xh in fp16, 128 half2 per node
__device__ float   g_h[(size_t)NN * 256];
__device__ int     g_cnt[NN];
__device__ int     g_off[NN + 1];
__device__ int     g_cur[NN];
__device__ int     g_csr[EE];
__device__ int     g_eid[EE];
__device__ float   g_asrc[NN * HEADS];
__device__ float   g_adst[NN * HEADS];
__device__ int     g_src[EE];
__device__ int     g_dst[EE];
__device__ int     g_is64;
__device__ int     g_blk[NBLK];
__device__ int     g_blkoff[NBLK];

// ---------------- helpers ---------------------------------------------------
__device__ __forceinline__ float lrelu(float x) { return x > 0.f ? x : 0.2f * x; }
__device__ __forceinline__ float elu(float x)   { return x > 0.f ? x : expf(x) - 1.f; }
__device__ __forceinline__ float wredsum(float v) {
    #pragma unroll
    for (int o = 16; o; o >>= 1) v += __shfl_xor_sync(0xffffffffu, v, o);
    return v;
}
__device__ __forceinline__ unsigned h2u(__half2 v) {
    return *reinterpret_cast<unsigned*>(&v);
}

// ---------------- edge index normalization ---------------------------------
__global__ void detect_kernel(const int* __restrict__ ei_raw) {
    if (threadIdx.x == 0) {
        int any = 0;
        #pragma unroll 1
        for (int i = 1; i < 256; i += 2) any |= ei_raw[i];
        g_is64 = (any == 0) ? 1 : 0;
    }
}

__global__ void zero_cnt() {
    int i = blockIdx.x * blockDim.x + threadIdx.x;
    if (i < NN) g_cnt[i] = 0;
}

__global__ void convert_edges(const int* __restrict__ ei_raw) {
    int e = blockIdx.x * blockDim.x + threadIdx.x;
    if (e >= EE) return;
    int s, d;
    if (g_is64) {
        s = ei_raw[2 * (size_t)e];
        d = ei_raw[2 * ((size_t)EE + e)];
    } else {
        s = ei_raw[e];
        d = ei_raw[EE + e];
    }
    s = min(max(s, 0), NN - 1);
    d = min(max(d, 0), NN - 1);
    g_src[e] = s;
    g_dst[e] = d;
    atomicAdd(&g_cnt[d], 1);
}

// ---------------- hierarchical scan -----------------------------------------
__global__ void scan1() {
    __shared__ int sh[SCAN_B];
    int t = threadIdx.x;
    int n = blockIdx.x * SCAN_B + t;
    int v = (n < NN) ? g_cnt[n] : 0;
    sh[t] = v;
    __syncthreads();
    #pragma unroll
    for (int off = 1; off < SCAN_B; off <<= 1) {
        int u = (t >= off) ? sh[t - off] : 0;
        __syncthreads();
        sh[t] += u;
        __syncthreads();
    }
    if (n < NN) g_off[n] = sh[t] - v;
    if (t == SCAN_B - 1) g_blk[blockIdx.x] = sh[t];
}

__global__ void scan2() {
    __shared__ int sh[SCAN_B];
    int t = threadIdx.x;
    int v = (t < NBLK) ? g_blk[t] : 0;
    sh[t] = v;
    __syncthreads();
    #pragma unroll
    for (int off = 1; off < SCAN_B; off <<= 1) {
        int u = (t >= off) ? sh[t - off] : 0;
        __syncthreads();
        sh[t] += u;
        __syncthreads();
    }
    if (t < NBLK) g_blkoff[t] = sh[t] - v;
    if (t == SCAN_B - 1) g_off[NN] = sh[t];
}

__global__ void scan3() {
    int n = blockIdx.x * SCAN_B + threadIdx.x;
    if (n >= NN) return;
    int o = g_off[n] + g_blkoff[blockIdx.x];
    g_off[n] = o;
    g_cur[n] = o;
}

__global__ void edge_fill_csr() {
    int e = blockIdx.x * blockDim.x + threadIdx.x;
    if (e >= EE) return;
    int pos = atomicAdd(&g_cur[g_dst[e]], 1);
    g_csr[pos] = g_src[e];
    g_eid[pos] = e;
}

// ---------------- fp16 tensor-core GEMM -------------------------------------
// C[M,256] = A[M,K] @ W[K,256] (+bias). BM=128, BN=128, BK=32.
// fp16 operands (same 10-bit mantissa as tf32), fp32 accumulate.
// A smem: half2 [128][20]. B smem: TRANSPOSED half [n=128][k=40] (= half2 [128][20]).
// mma.m16n8k16: k-step ks covers halves [ks*16, ks*16+16) = half2 [ks*8, ks*8+8).
__global__ void __launch_bounds__(256, 2)
gemm_f16(const float* __restrict__ A, int lda,
         const float* __restrict__ W,
         const float* __restrict__ bias,
         float* __restrict__ Cf, __half2* __restrict__ Ch, int ldc,
         int M, int K) {
    __shared__ __half2 As2[128][20];            // [row][k2]
    __shared__ __half  Bs_h[128][40];           // [n][k]  (transposed)

    int bm = blockIdx.y * 128;
    int bn = blockIdx.x * 128;
    int tid = threadIdx.x;
    int wid = tid >> 5;
    int lane = tid & 31;
    int gid = lane >> 2;
    int tig = lane & 3;
    int warp_m = (wid & 1) * 64;
    int warp_n = (wid >> 1) * 32;

    float c[4][4][4];
    #pragma unroll
    for (int i = 0; i < 4; i++)
        #pragma unroll
        for (int j = 0; j < 4; j++)
            #pragma unroll
            for (int r = 0; r < 4; r++) c[i][j][r] = 0.f;

    int ar = tid >> 1;               // 0..127
    int ac = (tid & 1) * 16;         // float col base: 0 or 16
    bool aok = (bm + ar) < M;
    const float* Aptr = A + (size_t)(bm + ar) * lda + ac;
    int br = tid >> 3;               // k row 0..31
    int bc = (tid & 7) * 16;         // n col base 0..112
    const float* Wptr = W + (size_t)br * 256 + bn + bc;

    for (int k0 = 0; k0 < K; k0 += 32) {
        // A tile: 128x32 floats -> half2
        #pragma unroll
        for (int j = 0; j < 4; j++) {
            float4 v = aok ? *(const float4*)(Aptr + k0 + j * 4)
                           : make_float4(0.f, 0.f, 0.f, 0.f);
            As2[ar][(ac >> 1) + 2 * j]     = __floats2half2_rn(v.x, v.y);
            As2[ar][(ac >> 1) + 2 * j + 1] = __floats2half2_rn(v.z, v.w);
        }
        // B tile: 32x128 floats -> transposed half [n][k]
        #pragma unroll
        for (int j = 0; j < 4; j++) {
            float4 v = *(const float4*)(Wptr + (size_t)k0 * 256 + j * 4);
            int n0 = bc + 4 * j;
            Bs_h[n0 + 0][br] = __float2half_rn(v.x);
            Bs_h[n0 + 1][br] = __float2half_rn(v.y);
            Bs_h[n0 + 2][br] = __float2half_rn(v.z);
            Bs_h[n0 + 3][br] = __float2half_rn(v.w);
        }
        __syncthreads();

        const __half2* Bs2 = reinterpret_cast<const __half2*>(&Bs_h[0][0]);  // [n][20]
        #pragma unroll
        for (int ks = 0; ks < 2; ks++) {
            int kh = ks * 8;   // half2 offset of this 16-wide k-step
            unsigned a[4][4], b[4][2];
            #pragma unroll
            for (int mt = 0; mt < 4; mt++) {
                int row = warp_m + mt * 16;
                a[mt][0] = h2u(As2[row + gid][kh + tig]);
                a[mt][1] = h2u(As2[row + gid + 8][kh + tig]);
                a[mt][2] = h2u(As2[row + gid][kh + tig + 4]);
                a[mt][3] = h2u(As2[row + gid + 8][kh + tig + 4]);
            }
            #pragma unroll
            for (int nt = 0; nt < 4; nt++) {
                int col = warp_n + nt * 8;
                b[nt][0] = h2u(Bs2[(col + gid) * 20 + kh + tig]);
                b[nt][1] = h2u(Bs2[(col + gid) * 20 + kh + tig + 4]);
            }
            #pragma unroll
            for (int mt = 0; mt < 4; mt++)
                #pragma unroll
                for (int nt = 0; nt < 4; nt++) {
                    asm volatile(
                        "mma.sync.aligned.m16n8k16.row.col.f32.f16.f16.f32 "
                        "{%0,%1,%2,%3}, {%4,%5,%6,%7}, {%8,%9}, {%0,%1,%2,%3};"
                        : "+f"(c[mt][nt][0]), "+f"(c[mt][nt][1]),
                          "+f"(c[mt][nt][2]), "+f"(c[mt][nt][3])
                        : "r"(a[mt][0]), "r"(a[mt][1]), "r"(a[mt][2]), "r"(a[mt][3]),
                          "r"(b[nt][0]), "r"(b[nt][1]));
                }
        }
        __syncthreads();
    }

    #pragma unroll
    for (int mt = 0; mt < 4; mt++) {
        int r0 = bm + warp_m + mt * 16 + gid;
        #pragma unroll
        for (int nt = 0; nt < 4; nt++) {
            int col = bn + warp_n + nt * 8 + 2 * tig;
            float bx = 0.f, by = 0.f;
            if (bias) { bx = bias[col]; by = bias[col + 1]; }
            float x0 = c[mt][nt][0] + bx, y0 = c[mt][nt][1] + by;
            float x1 = c[mt][nt][2] + bx, y1 = c[mt][nt][3] + by;
            if (Cf) {
                if (r0 < M)     *(float2*)(Cf + (size_t)r0 * ldc + col) = make_float2(x0, y0);
                if (r0 + 8 < M) *(float2*)(Cf + (size_t)(r0 + 8) * ldc + col) = make_float2(x1, y1);
            }
            if (Ch) {
                if (r0 < M)     Ch[(size_t)r0 * 128 + (col >> 1)]       = __floats2half2_rn(x0, y0);
                if (r0 + 8 < M) Ch[(size_t)(r0 + 8) * 128 + (col >> 1)] = __floats2half2_rn(x1, y1);
            }
        }
    }
}

// ---------------- edge mean (CSR gather) + edge_proj ------------------------
__global__ void edgeproj_kernel(const float* __restrict__ eattr,
                                const float* __restrict__ Wep,
                                const float* __restrict__ bep) {
    __shared__ float sW[EDGE_DIM][256];
    __shared__ float snef[16][EDGE_DIM];
    int tid = threadIdx.x;
    for (int i = tid; i < EDGE_DIM * 256; i += 256)
        sW[i >> 8][i & 255] = Wep[i];

    int g = tid >> 4;
    int j = tid & 15;
    int n = blockIdx.x * 16 + g;

    float s = 0.f;
    int deg = 0;
    if (n < NN) {
        int off = g_off[n];
        deg = g_off[n + 1] - off;
        for (int e = 0; e < deg; e++) {
            int eid = g_eid[off + e];
            s += eattr[(size_t)eid * EDGE_DIM + j];
        }
    }
    snef[g][j] = s / fmaxf((float)deg, 1.0f);
    __syncthreads();

    if (n < NN) {
        int c0 = j * 16;
        float acc[16];
        #pragma unroll
        for (int c = 0; c < 16; c++) acc[c] = bep[c0 + c];
        #pragma unroll
        for (int k = 0; k < EDGE_DIM; k++) {
            float v = snef[g][k];
            #pragma unroll
            for (int c = 0; c < 16; c++) acc[c] += v * sW[k][c0 + c];
        }
        float* outp = g_xcat + (size_t)n * 512 + 256 + c0;
        #pragma unroll
        for (int c = 0; c < 16; c += 4)
            *(float4*)(outp + c) = make_float4(acc[c], acc[c + 1], acc[c + 2], acc[c + 3]);
    }
}

// ---------------- attention dot products (half2 input) ----------------------
__global__ void attn_dots(const float* __restrict__ as_p,
                          const float* __restrict__ ad_p) {
    int n = blockIdx.x;
    int h = threadIdx.x >> 5;
    int l = threadIdx.x & 31;
    const __half2* row = g_xh_h + (size_t)n * 128 + h * 32;
    float2 x = __half22float2(row[l]);
    int c = 2 * l;
    float s = x.x * as_p[h * CH + c] + x.y * as_p[h * CH + c + 1];
    float d = x.x * ad_p[h * CH + c] + x.y * ad_p[h * CH + c + 1];
    s = wredsum(s);
    d = wredsum(d);
    if (l == 0) {
        g_asrc[n * HEADS + h] = s;
        g_adst[n * HEADS + h] = d;
    }
}

// ---------------- GAT aggregation: single pass, half2 gather ----------------
__global__ void gat_aggregate(const float* __restrict__ bias,
                              float* __restrict__ out) {
    int n = blockIdx.x;
    int h = threadIdx.x >> 5;
    int l = threadIdx.x & 31;
    int off = g_off[n];
    int deg = g_off[n + 1] - off;
    float adst = g_adst[n * HEADS + h];

    const __half2* xr = g_xh_h + (size_t)n * 128 + h * 32;
    float2 xs = __half22float2(xr[l]);
    float wslf = expf(fminf(lrelu(g_asrc[n * HEADS + h] + adst), 60.f));
    float ds = wslf;
    float a0 = wslf * xs.x;
    float a1 = wslf * xs.y;

    int e = 0;
    for (; e + 1 < deg; e += 2) {
        int s0 = g_csr[off + e];
        int s1 = g_csr[off + e + 1];
        float w0 = expf(fminf(lrelu(g_asrc[s0 * HEADS + h] + adst), 60.f));
        float w1 = expf(fminf(lrelu(g_asrc[s1 * HEADS + h] + adst), 60.f));
        float2 v0 = __half22float2(g_xh_h[(size_t)s0 * 128 + h * 32 + l]);
        float2 v1 = __half22float2(g_xh_h[(size_t)s1 * 128 + h * 32 + l]);
        ds += w0 + w1;
        a0 += w0 * v0.x + w1 * v1.x;
        a1 += w0 * v0.y + w1 * v1.y;
    }
    if (e < deg) {
        int s0 = g_csr[off + e];
        float w0 = expf(fminf(lrelu(g_asrc[s0 * HEADS + h] + adst), 60.f));
        float2 v0 = __half22float2(g_xh_h[(size_t)s0 * 128 + h * 32 + l]);
        ds += w0;
        a0 += w0 * v0.x;
        a1 += w0 * v0.y;
    }

    float inv = 1.0f / ds;
    int c = h * CH + 2 * l;
    float b0 = bias[c], b1 = bias[c + 1];
    float2 o = make_float2(elu(a0 * inv + b0), elu(a1 * inv + b1));
    *(float2*)(out + (size_t)n * 256 + c) = o;
}

// ---------------- launch ----------------------------------------------------
extern "C" void kernel_launch(void* const* d_in, const int* in_sizes, int n_in,
                              void* d_out, int out_size) {
    const float* node_feats = (const float*)d_in[0];
    const float* edge_attr  = (const float*)d_in[1];
    const float* Wnp = (const float*)d_in[2];
    const float* bnp = (const float*)d_in[3];
    const float* Wep = (const float*)d_in[4];
    const float* bep = (const float*)d_in[5];
    const float* Wg1 = (const float*)d_in[6];
    const float* as1 = (const float*)d_in[7];
    const float* ad1 = (const float*)d_in[8];
    const float* bg1 = (const float*)d_in[9];
    const float* Wg2 = (const float*)d_in[10];
    const float* as2 = (const float*)d_in[11];
    const float* ad2 = (const float*)d_in[12];
    const float* bg2 = (const float*)d_in[13];
    const float* Wo  = (const float*)d_in[14];
    const float* bo  = (const float*)d_in[15];
    const int* ei_raw = (const int*)d_in[16];
    float* out = (float*)d_out;

    float* xcat;   cudaGetSymbolAddress((void**)&xcat, g_xcat);
    __half2* xhh;  cudaGetSymbolAddress((void**)&xhh, g_xh_h);
    float* hbuf;   cudaGetSymbolAddress((void**)&hbuf, g_h);

    const int EB = (EE + 255) / 256;

    detect_kernel<<<1, 32>>>(ei_raw);
    zero_cnt<<<NBLK, SCAN_B>>>();
    convert_edges<<<EB, 256>>>(ei_raw);
    scan1<<<NBLK, SCAN_B>>>();
    scan2<<<1, SCAN_B>>>();
    scan3<<<NBLK, SCAN_B>>>();
    edge_fill_csr<<<EB, 256>>>();

    dim3 ggrid(2, (NN + 127) / 128);

    // node_proj -> xcat[:, :256] (fp32)
    gemm_f16<<<ggrid, 256>>>(node_feats, NODE_IN, Wnp, bnp, xcat, nullptr, 512, NN, NODE_IN);
    // edge mean + edge_proj -> xcat[:, 256:512]
    edgeproj_kernel<<<(NN + 15) / 16, 256>>>(edge_attr, Wep, bep);

    // ---- GAT layer 1 : xh in fp16 ----
    gemm_f16<<<ggrid, 256>>>(xcat, 512, Wg1, nullptr, nullptr, xhh, 256, NN, 512);
    attn_dots<<<NN, 128>>>(as1, ad1);
    gat_aggregate<<<NN, 128>>>(bg1, hbuf);

    // ---- GAT layer 2 ----
    gemm_f16<<<ggrid, 256>>>(hbuf, 256, Wg2, nullptr, nullptr, xhh, 256, NN, 256);
    attn_dots<<<NN, 128>>>(as2, ad2);
    gat_aggregate<<<NN, 128>>>(bg2, hbuf);

    // ---- out_proj -> d_out ----
    gemm_f16<<<ggrid, 256>>>(hbuf, 256, Wo, bo, out, nullptr, 256, NN, 256);
}

// round 13
// speedup vs baseline: 1.8598x; 1.8598x over previous
#include <cuda_runtime.h>
#include <cuda_fp16.h>
#include <cuda_bf16.h>
#include <math.h>

#define NN 50000
#define EE 800000
#define NODE_IN 128
#define HID 256
#define OUT_D 256
#define EDGE_DIM 16
#define HEADS 4
#define CH 64

#define SCAN_B 256
#define NBLK ((NN + SCAN_B - 1) / SCAN_B)   // 196

// B smem row: 128 halves data + 8 pad = 136 halves = 272 B (16B-aligned rows)
#define BSTRIDE 136

// ---------------- scratch (static device globals) ---------------------------
__device__ float   g_xcat[(size_t)NN * 512];
__device__ __half2 g_xh_h[(size_t)NN * 128];   // xh in fp16, 128 half2 per node
__device__ float   g_h[(size_t)NN * 256];
__device__ int     g_cnt[NN];
__device__ int     g_off[NN + 1];
__device__ int     g_cur[NN];
__device__ int     g_csr[EE];
__device__ int     g_eid[EE];
__device__ float   g_asrc[NN * HEADS];
__device__ float   g_adst[NN * HEADS];
__device__ int     g_src[EE];
__device__ int     g_dst[EE];
__device__ int     g_is64;
__device__ int     g_blk[NBLK];
__device__ int     g_blkoff[NBLK];

// ---------------- helpers ---------------------------------------------------
__device__ __forceinline__ float lrelu(float x) { return x > 0.f ? x : 0.2f * x; }
__device__ __forceinline__ float elu(float x)   { return x > 0.f ? x : expf(x) - 1.f; }
__device__ __forceinline__ float wredsum(float v) {
    #pragma unroll
    for (int o = 16; o; o >>= 1) v += __shfl_xor_sync(0xffffffffu, v, o);
    return v;
}
__device__ __forceinline__ unsigned h2u(__half2 v) {
    return *reinterpret_cast<unsigned*>(&v);
}

// ---------------- edge index normalization ---------------------------------
__global__ void detect_kernel(const int* __restrict__ ei_raw) {
    if (threadIdx.x == 0) {
        int any = 0;
        #pragma unroll 1
        for (int i = 1; i < 256; i += 2) any |= ei_raw[i];
        g_is64 = (any == 0) ? 1 : 0;
    }
}

__global__ void zero_cnt() {
    int i = blockIdx.x * blockDim.x + threadIdx.x;
    if (i < NN) g_cnt[i] = 0;
}

__global__ void convert_edges(const int* __restrict__ ei_raw) {
    int e = blockIdx.x * blockDim.x + threadIdx.x;
    if (e >= EE) return;
    int s, d;
    if (g_is64) {
        s = ei_raw[2 * (size_t)e];
        d = ei_raw[2 * ((size_t)EE + e)];
    } else {
        s = ei_raw[e];
        d = ei_raw[EE + e];
    }
    s = min(max(s, 0), NN - 1);
    d = min(max(d, 0), NN - 1);
    g_src[e] = s;
    g_dst[e] = d;
    atomicAdd(&g_cnt[d], 1);
}

// ---------------- hierarchical scan -----------------------------------------
__global__ void scan1() {
    __shared__ int sh[SCAN_B];
    int t = threadIdx.x;
    int n = blockIdx.x * SCAN_B + t;
    int v = (n < NN) ? g_cnt[n] : 0;
    sh[t] = v;
    __syncthreads();
    #pragma unroll
    for (int off = 1; off < SCAN_B; off <<= 1) {
        int u = (t >= off) ? sh[t - off] : 0;
        __syncthreads();
        sh[t] += u;
        __syncthreads();
    }
    if (n < NN) g_off[n] = sh[t] - v;
    if (t == SCAN_B - 1) g_blk[blockIdx.x] = sh[t];
}

__global__ void scan2() {
    __shared__ int sh[SCAN_B];
    int t = threadIdx.x;
    int v = (t < NBLK) ? g_blk[t] : 0;
    sh[t] = v;
    __syncthreads();
    #pragma unroll
    for (int off = 1; off < SCAN_B; off <<= 1) {
        int u = (t >= off) ? sh[t - off] : 0;
        __syncthreads();
        sh[t] += u;
        __syncthreads();
    }
    if (t < NBLK) g_blkoff[t] = sh[t] - v;
    if (t == SCAN_B - 1) g_off[NN] = sh[t];
}

__global__ void scan3() {
    int n = blockIdx.x * SCAN_B + threadIdx.x;
    if (n >= NN) return;
    int o = g_off[n] + g_blkoff[blockIdx.x];
    g_off[n] = o;
    g_cur[n] = o;
}

__global__ void edge_fill_csr() {
    int e = blockIdx.x * blockDim.x + threadIdx.x;
    if (e >= EE) return;
    int pos = atomicAdd(&g_cur[g_dst[e]], 1);
    g_csr[pos] = g_src[e];
    g_eid[pos] = e;
}

// ---------------- fp16 tensor-core GEMM (ldmatrix.trans for B) --------------
// C[M,256] = A[M,K] @ W[K,256] (+bias). BM=128, BN=128, BK=32.
// A smem: half2 [128][20] (row-major, k contiguous); direct fragment LDS.
// B smem: half [32][BSTRIDE] (k rows, n contiguous, NOT transposed);
//         stores are lane-per-float4 STS.64 (conflict-free);
//         fragments via ldmatrix.x4.trans.
__global__ void __launch_bounds__(256, 2)
gemm_f16(const float* __restrict__ A, int lda,
         const float* __restrict__ W,
         const float* __restrict__ bias,
         float* __restrict__ Cf, __half2* __restrict__ Ch, int ldc,
         int M, int K) {
    __shared__ __half2 As2[128][20];              // [row][k2]
    __shared__ __half  Bs_h[32][BSTRIDE];         // [k][n]

    int bm = blockIdx.y * 128;
    int bn = blockIdx.x * 128;
    int tid = threadIdx.x;
    int wid = tid >> 5;
    int lane = tid & 31;
    int gid = lane >> 2;
    int tig = lane & 3;
    int warp_m = (wid & 1) * 64;
    int warp_n = (wid >> 1) * 32;

    float c[4][4][4];
    #pragma unroll
    for (int i = 0; i < 4; i++)
        #pragma unroll
        for (int j = 0; j < 4; j++)
            #pragma unroll
            for (int r = 0; r < 4; r++) c[i][j][r] = 0.f;

    // A gmem mapping: thread covers 16 consecutive floats of one row
    int ar = tid >> 1;               // 0..127
    int ac = (tid & 1) * 16;         // 0 or 16
    bool aok = (bm + ar) < M;
    const float* Aptr = A + (size_t)(bm + ar) * lda + ac;
    // B gmem mapping: warp wid covers rows wid*4..wid*4+3; lane covers 4 floats
    int brow0 = wid * 4;
    const float* Wbase = W + bn + 4 * lane;

    // ldmatrix per-lane source address (constant across k-tiles up to krow)
    int lm_krow = lane & 15;             // 0..15 within k-step
    int lm_noff = (lane >> 4) * 8;       // 0 or 8

    for (int k0 = 0; k0 < K; k0 += 32) {
        // A tile: 128x32 floats -> half2 smem
        #pragma unroll
        for (int j = 0; j < 4; j++) {
            float4 v = aok ? *(const float4*)(Aptr + k0 + j * 4)
                           : make_float4(0.f, 0.f, 0.f, 0.f);
            As2[ar][(ac >> 1) + 2 * j]     = __floats2half2_rn(v.x, v.y);
            As2[ar][(ac >> 1) + 2 * j + 1] = __floats2half2_rn(v.z, v.w);
        }
        // B tile: 32x128 floats -> half [k][n] smem (coalesced, conflict-free)
        #pragma unroll
        for (int it = 0; it < 4; it++) {
            int row = brow0 + it;
            float4 v = *(const float4*)(Wbase + (size_t)(k0 + row) * 256);
            __half2 h0 = __floats2half2_rn(v.x, v.y);
            __half2 h1 = __floats2half2_rn(v.z, v.w);
            *(uint2*)&Bs_h[row][4 * lane] = make_uint2(h2u(h0), h2u(h1));
        }
        __syncthreads();

        #pragma unroll
        for (int ks = 0; ks < 2; ks++) {
            int kh = ks * 8;   // half2 offset of this 16-wide k-step (A side)
            unsigned a[4][4], b[4][2];
            #pragma unroll
            for (int mt = 0; mt < 4; mt++) {
                int row = warp_m + mt * 16;
                a[mt][0] = h2u(As2[row + gid][kh + tig]);
                a[mt][1] = h2u(As2[row + gid + 8][kh + tig]);
                a[mt][2] = h2u(As2[row + gid][kh + tig + 4]);
                a[mt][3] = h2u(As2[row + gid + 8][kh + tig + 4]);
            }
            // B fragments: 2x ldmatrix.x4.trans, each covers two n-groups of 8
            #pragma unroll
            for (int p = 0; p < 2; p++) {
                int col = warp_n + p * 16 + lm_noff;
                int krow = ks * 16 + lm_krow;
                unsigned addr = (unsigned)__cvta_generic_to_shared(&Bs_h[krow][col]);
                unsigned r0, r1, r2, r3;
                asm volatile(
                    "ldmatrix.sync.aligned.m8n8.x4.trans.shared.b16 "
                    "{%0,%1,%2,%3}, [%4];"
                    : "=r"(r0), "=r"(r1), "=r"(r2), "=r"(r3)
                    : "r"(addr));
                b[2 * p][0] = r0;
                b[2 * p][1] = r1;
                b[2 * p + 1][0] = r2;
                b[2 * p + 1][1] = r3;
            }
            #pragma unroll
            for (int mt = 0; mt < 4; mt++)
                #pragma unroll
                for (int nt = 0; nt < 4; nt++) {
                    asm volatile(
                        "mma.sync.aligned.m16n8k16.row.col.f32.f16.f16.f32 "
                        "{%0,%1,%2,%3}, {%4,%5,%6,%7}, {%8,%9}, {%0,%1,%2,%3};"
                        : "+f"(c[mt][nt][0]), "+f"(c[mt][nt][1]),
                          "+f"(c[mt][nt][2]), "+f"(c[mt][nt][3])
                        : "r"(a[mt][0]), "r"(a[mt][1]), "r"(a[mt][2]), "r"(a[mt][3]),
                          "r"(b[nt][0]), "r"(b[nt][1]));
                }
        }
        __syncthreads();
    }

    #pragma unroll
    for (int mt = 0; mt < 4; mt++) {
        int r0 = bm + warp_m + mt * 16 + gid;
        #pragma unroll
        for (int nt = 0; nt < 4; nt++) {
            int col = bn + warp_n + nt * 8 + 2 * tig;
            float bx = 0.f, by = 0.f;
            if (bias) { bx = bias[col]; by = bias[col + 1]; }
            float x0 = c[mt][nt][0] + bx, y0 = c[mt][nt][1] + by;
            float x1 = c[mt][nt][2] + bx, y1 = c[mt][nt][3] + by;
            if (Cf) {
                if (r0 < M)     *(float2*)(Cf + (size_t)r0 * ldc + col) = make_float2(x0, y0);
                if (r0 + 8 < M) *(float2*)(Cf + (size_t)(r0 + 8) * ldc + col) = make_float2(x1, y1);
            }
            if (Ch) {
                if (r0 < M)     Ch[(size_t)r0 * 128 + (col >> 1)]       = __floats2half2_rn(x0, y0);
                if (r0 + 8 < M) Ch[(size_t)(r0 + 8) * 128 + (col >> 1)] = __floats2half2_rn(x1, y1);
            }
        }
    }
}

// ---------------- edge mean (CSR gather) + edge_proj ------------------------
__global__ void edgeproj_kernel(const float* __restrict__ eattr,
                                const float* __restrict__ Wep,
                                const float* __restrict__ bep) {
    __shared__ float sW[EDGE_DIM][256];
    __shared__ float snef[16][EDGE_DIM];
    int tid = threadIdx.x;
    for (int i = tid; i < EDGE_DIM * 256; i += 256)
        sW[i >> 8][i & 255] = Wep[i];

    int g = tid >> 4;
    int j = tid & 15;
    int n = blockIdx.x * 16 + g;

    float s = 0.f;
    int deg = 0;
    if (n < NN) {
        int off = g_off[n];
        deg = g_off[n + 1] - off;
        for (int e = 0; e < deg; e++) {
            int eid = g_eid[off + e];
            s += eattr[(size_t)eid * EDGE_DIM + j];
        }
    }
    snef[g][j] = s / fmaxf((float)deg, 1.0f);
    __syncthreads();

    if (n < NN) {
        int c0 = j * 16;
        float acc[16];
        #pragma unroll
        for (int c = 0; c < 16; c++) acc[c] = bep[c0 + c];
        #pragma unroll
        for (int k = 0; k < EDGE_DIM; k++) {
            float v = snef[g][k];
            #pragma unroll
            for (int c = 0; c < 16; c++) acc[c] += v * sW[k][c0 + c];
        }
        float* outp = g_xcat + (size_t)n * 512 + 256 + c0;
        #pragma unroll
        for (int c = 0; c < 16; c += 4)
            *(float4*)(outp + c) = make_float4(acc[c], acc[c + 1], acc[c + 2], acc[c + 3]);
    }
}

// ---------------- attention dot products (half2 input) ----------------------
__global__ void attn_dots(const float* __restrict__ as_p,
                          const float* __restrict__ ad_p) {
    int n = blockIdx.x;
    int h = threadIdx.x >> 5;
    int l = threadIdx.x & 31;
    const __half2* row = g_xh_h + (size_t)n * 128 + h * 32;
    float2 x = __half22float2(row[l]);
    int c = 2 * l;
    float s = x.x * as_p[h * CH + c] + x.y * as_p[h * CH + c + 1];
    float d = x.x * ad_p[h * CH + c] + x.y * ad_p[h * CH + c + 1];
    s = wredsum(s);
    d = wredsum(d);
    if (l == 0) {
        g_asrc[n * HEADS + h] = s;
        g_adst[n * HEADS + h] = d;
    }
}

// ---------------- GAT aggregation: single pass, half2 gather ----------------
__global__ void gat_aggregate(const float* __restrict__ bias,
                              float* __restrict__ out) {
    int n = blockIdx.x;
    int h = threadIdx.x >> 5;
    int l = threadIdx.x & 31;
    int off = g_off[n];
    int deg = g_off[n + 1] - off;
    float adst = g_adst[n * HEADS + h];

    const __half2* xr = g_xh_h + (size_t)n * 128 + h * 32;
    float2 xs = __half22float2(xr[l]);
    float wslf = expf(fminf(lrelu(g_asrc[n * HEADS + h] + adst), 60.f));
    float ds = wslf;
    float a0 = wslf * xs.x;
    float a1 = wslf * xs.y;

    int e = 0;
    for (; e + 1 < deg; e += 2) {
        int s0 = g_csr[off + e];
        int s1 = g_csr[off + e + 1];
        float w0 = expf(fminf(lrelu(g_asrc[s0 * HEADS + h] + adst), 60.f));
        float w1 = expf(fminf(lrelu(g_asrc[s1 * HEADS + h] + adst), 60.f));
        float2 v0 = __half22float2(g_xh_h[(size_t)s0 * 128 + h * 32 + l]);
        float2 v1 = __half22float2(g_xh_h[(size_t)s1 * 128 + h * 32 + l]);
        ds += w0 + w1;
        a0 += w0 * v0.x + w1 * v1.x;
        a1 += w0 * v0.y + w1 * v1.y;
    }
    if (e < deg) {
        int s0 = g_csr[off + e];
        float w0 = expf(fminf(lrelu(g_asrc[s0 * HEADS + h] + adst), 60.f));
        float2 v0 = __half22float2(g_xh_h[(size_t)s0 * 128 + h * 32 + l]);
        ds += w0;
        a0 += w0 * v0.x;
        a1 += w0 * v0.y;
    }

    float inv = 1.0f / ds;
    int c = h * CH + 2 * l;
    float b0 = bias[c], b1 = bias[c + 1];
    float2 o = make_float2(elu(a0 * inv + b0), elu(a1 * inv + b1));
    *(float2*)(out + (size_t)n * 256 + c) = o;
}

// ---------------- launch ----------------------------------------------------
extern "C" void kernel_launch(void* const* d_in, const int* in_sizes, int n_in,
                              void* d_out, int out_size) {
    const float* node_feats = (const float*)d_in[0];
    const float* edge_attr  = (const float*)d_in[1];
    const float* Wnp = (const float*)d_in[2];
    const float* bnp = (const float*)d_in[3];
    const float* Wep = (const float*)d_in[4];
    const float* bep = (const float*)d_in[5];
    const float* Wg1 = (const float*)d_in[6];
    const float* as1 = (const float*)d_in[7];
    const float* ad1 = (const float*)d_in[8];
    const float* bg1 = (const float*)d_in[9];
    const float* Wg2 = (const float*)d_in[10];
    const float* as2 = (const float*)d_in[11];
    const float* ad2 = (const float*)d_in[12];
    const float* bg2 = (const float*)d_in[13];
    const float* Wo  = (const float*)d_in[14];
    const float* bo  = (const float*)d_in[15];
    const int* ei_raw = (const int*)d_in[16];
    float* out = (float*)d_out;

    float* xcat;   cudaGetSymbolAddress((void**)&xcat, g_xcat);
    __half2* xhh;  cudaGetSymbolAddress((void**)&xhh, g_xh_h);
    float* hbuf;   cudaGetSymbolAddress((void**)&hbuf, g_h);

    const int EB = (EE + 255) / 256;

    detect_kernel<<<1, 32>>>(ei_raw);
    zero_cnt<<<NBLK, SCAN_B>>>();
    convert_edges<<<EB, 256>>>(ei_raw);
    scan1<<<NBLK, SCAN_B>>>();
    scan2<<<1, SCAN_B>>>();
    scan3<<<NBLK, SCAN_B>>>();
    edge_fill_csr<<<EB, 256>>>();

    dim3 ggrid(2, (NN + 127) / 128);

    // node_proj -> xcat[:, :256] (fp32)
    gemm_f16<<<ggrid, 256>>>(node_feats, NODE_IN, Wnp, bnp, xcat, nullptr, 512, NN, NODE_IN);
    // edge mean + edge_proj -> xcat[:, 256:512]
    edgeproj_kernel<<<(NN + 15) / 16, 256>>>(edge_attr, Wep, bep);

    // ---- GAT layer 1 : xh in fp16 ----
    gemm_f16<<<ggrid, 256>>>(xcat, 512, Wg1, nullptr, nullptr, xhh, 256, NN, 512);
    attn_dots<<<NN, 128>>>(as1, ad1);
    gat_aggregate<<<NN, 128>>>(bg1, hbuf);

    // ---- GAT layer 2 ----
    gemm_f16<<<ggrid, 256>>>(hbuf, 256, Wg2, nullptr, nullptr, xhh, 256, NN, 256);
    attn_dots<<<NN, 128>>>(as2, ad2);
    gat_aggregate<<<NN, 128>>>(bg2, hbuf);

    // ---- out_proj -> d_out ----
    gemm_f16<<<ggrid, 256>>>(hbuf, 256, Wo, bo, out, nullptr, 256, NN, 256);
}

// round 14
// speedup vs baseline: 2.0740x; 1.1152x over previous
#include <cuda_runtime.h>
#include <cuda_fp16.h>
#include <cuda_bf16.h>
#include <math.h>

#define NN 50000
#define EE 800000
#define NODE_IN 128
#define HID 256
#define OUT_D 256
#define EDGE_DIM 16
#define HEADS 4
#define CH 64

#define SCAN_B 256
#define NBLK ((NN + SCAN_B - 1) / SCAN_B)   // 196

#define ASTR 40     // A smem row: 32 halves + 8 pad (80B)
#define BSTR 136    // B smem row: 128 halves + 8 pad (272B)

// ---------------- scratch (static device globals) ---------------------------
__device__ __half  g_nf_h[(size_t)NN * NODE_IN];     // node_feats fp16
__device__ __half  g_xcat_h[(size_t)NN * 512];       // concat input, fp16
__device__ __half2 g_xh_h[(size_t)NN * 128];         // xh fp16
__device__ __half2 g_hh[(size_t)NN * 128];           // layer output fp16
__device__ __half  g_wnp_h[NODE_IN * 256];
__device__ __half  g_wg1_h[512 * 256];
__device__ __half  g_wg2_h[256 * 256];
__device__ __half  g_wo_h[256 * 256];
__device__ int     g_cnt[NN];
__device__ int     g_off[NN + 1];
__device__ int     g_cur[NN];
__device__ int     g_csr[EE];
__device__ int     g_eid[EE];
__device__ float   g_asrc[NN * HEADS];
__device__ float   g_adst[NN * HEADS];
__device__ int     g_src[EE];
__device__ int     g_dst[EE];
__device__ int     g_is64;
__device__ int     g_blk[NBLK];
__device__ int     g_blkoff[NBLK];

// ---------------- helpers ---------------------------------------------------
__device__ __forceinline__ float lrelu(float x) { return x > 0.f ? x : 0.2f * x; }
__device__ __forceinline__ float elu(float x)   { return x > 0.f ? x : expf(x) - 1.f; }
__device__ __forceinline__ float wredsum(float v) {
    #pragma unroll
    for (int o = 16; o; o >>= 1) v += __shfl_xor_sync(0xffffffffu, v, o);
    return v;
}
__device__ __forceinline__ unsigned h2u(__half2 v) {
    return *reinterpret_cast<unsigned*>(&v);
}

// ---------------- fp32 -> fp16 conversion -----------------------------------
__global__ void f2h_kernel(const float* __restrict__ src, __half2* __restrict__ dst, int n2) {
    int i = blockIdx.x * blockDim.x + threadIdx.x;
    if (i < n2) {
        float2 v = reinterpret_cast<const float2*>(src)[i];
        dst[i] = __floats2half2_rn(v.x, v.y);
    }
}

// ---------------- edge index normalization ---------------------------------
__global__ void detect_kernel(const int* __restrict__ ei_raw) {
    if (threadIdx.x == 0) {
        int any = 0;
        #pragma unroll 1
        for (int i = 1; i < 256; i += 2) any |= ei_raw[i];
        g_is64 = (any == 0) ? 1 : 0;
    }
}

__global__ void zero_cnt() {
    int i = blockIdx.x * blockDim.x + threadIdx.x;
    if (i < NN) g_cnt[i] = 0;
}

__global__ void convert_edges(const int* __restrict__ ei_raw) {
    int e = blockIdx.x * blockDim.x + threadIdx.x;
    if (e >= EE) return;
    int s, d;
    if (g_is64) {
        s = ei_raw[2 * (size_t)e];
        d = ei_raw[2 * ((size_t)EE + e)];
    } else {
        s = ei_raw[e];
        d = ei_raw[EE + e];
    }
    s = min(max(s, 0), NN - 1);
    d = min(max(d, 0), NN - 1);
    g_src[e] = s;
    g_dst[e] = d;
    atomicAdd(&g_cnt[d], 1);
}

// ---------------- hierarchical scan -----------------------------------------
__global__ void scan1() {
    __shared__ int sh[SCAN_B];
    int t = threadIdx.x;
    int n = blockIdx.x * SCAN_B + t;
    int v = (n < NN) ? g_cnt[n] : 0;
    sh[t] = v;
    __syncthreads();
    #pragma unroll
    for (int off = 1; off < SCAN_B; off <<= 1) {
        int u = (t >= off) ? sh[t - off] : 0;
        __syncthreads();
        sh[t] += u;
        __syncthreads();
    }
    if (n < NN) g_off[n] = sh[t] - v;
    if (t == SCAN_B - 1) g_blk[blockIdx.x] = sh[t];
}

__global__ void scan2() {
    __shared__ int sh[SCAN_B];
    int t = threadIdx.x;
    int v = (t < NBLK) ? g_blk[t] : 0;
    sh[t] = v;
    __syncthreads();
    #pragma unroll
    for (int off = 1; off < SCAN_B; off <<= 1) {
        int u = (t >= off) ? sh[t - off] : 0;
        __syncthreads();
        sh[t] += u;
        __syncthreads();
    }
    if (t < NBLK) g_blkoff[t] = sh[t] - v;
    if (t == SCAN_B - 1) g_off[NN] = sh[t];
}

__global__ void scan3() {
    int n = blockIdx.x * SCAN_B + threadIdx.x;
    if (n >= NN) return;
    int o = g_off[n] + g_blkoff[blockIdx.x];
    g_off[n] = o;
    g_cur[n] = o;
}

__global__ void edge_fill_csr() {
    int e = blockIdx.x * blockDim.x + threadIdx.x;
    if (e >= EE) return;
    int pos = atomicAdd(&g_cur[g_dst[e]], 1);
    g_csr[pos] = g_src[e];
    g_eid[pos] = e;
}

// ---------------- fp16 GEMM, cp.async double-buffered -----------------------
// C[M,256] = A[M,K](half) @ W[K,256](half) (+bias fp32).
// BM=128, BN=128, BK=32, 8 warps (2m x 4n), m16n8k16, fp32 accum.
// A smem [128][ASTR], fragments via ldmatrix.x4; B smem [32][BSTR],
// fragments via ldmatrix.x4.trans. Loads via cp.async 16B.
__global__ void __launch_bounds__(256, 2)
gemm_h(const __half* __restrict__ A, int lda,
       const __half* __restrict__ W,
       const float* __restrict__ bias,
       float* __restrict__ Cf, int ldc_f,
       __half2* __restrict__ Ch, int ldc_h,
       int M, int K) {
    __shared__ __half As_s[2][128][ASTR];
    __shared__ __half Bs_s[2][32][BSTR];

    int bm = blockIdx.y * 128;
    int bn = blockIdx.x * 128;
    int tid = threadIdx.x;
    int wid = tid >> 5;
    int lane = tid & 31;
    int gid = lane >> 2;
    int tig = lane & 3;
    int warp_m = (wid & 1) * 64;
    int warp_n = (wid >> 1) * 32;

    float c[4][4][4];
    #pragma unroll
    for (int i = 0; i < 4; i++)
        #pragma unroll
        for (int j = 0; j < 4; j++)
            #pragma unroll
            for (int r = 0; r < 4; r++) c[i][j][r] = 0.f;

    // cp.async chunk mapping (2 chunks each of A and B per thread per stage)
    // A chunk c (0..511): row=c>>2, kc=(c&3)*8 halves
    // B chunk c (0..511): krow=c>>4, nc=(c&15)*8 halves
    int a_row0 = tid >> 2,        a_kc0 = (tid & 3) * 8;
    int a_row1 = (tid + 256) >> 2, a_kc1 = (tid & 3) * 8;   // c+256: row += 64, same kc
    a_row1 = a_row0 + 64;
    int b_kr0 = tid >> 4,          b_nc0 = (tid & 15) * 8;
    int b_kr1 = b_kr0 + 16,        b_nc1 = b_nc0;

    int sz_a0 = (bm + a_row0 < M) ? 16 : 0;
    int sz_a1 = (bm + a_row1 < M) ? 16 : 0;
    const __half* Asrc0 = A + (size_t)(bm + a_row0) * lda + a_kc0;
    const __half* Asrc1 = A + (size_t)(bm + a_row1) * lda + a_kc1;
    const __half* Bsrc0 = W + (size_t)b_kr0 * 256 + bn + b_nc0;
    const __half* Bsrc1 = W + (size_t)b_kr1 * 256 + bn + b_nc1;

    int ntiles = K >> 5;

    // ldmatrix source coords
    int lmA_row = lane & 15;
    int lmA_kh = (lane >> 4) * 8;
    int lmB_kr = lane & 15;
    int lmB_no = (lane >> 4) * 8;

    #define LOAD_STAGE(buf, k0)                                                     \
    {                                                                               \
        unsigned da0 = (unsigned)__cvta_generic_to_shared(&As_s[buf][a_row0][a_kc0]); \
        unsigned da1 = (unsigned)__cvta_generic_to_shared(&As_s[buf][a_row1][a_kc1]); \
        unsigned db0 = (unsigned)__cvta_generic_to_shared(&Bs_s[buf][b_kr0][b_nc0]); \
        unsigned db1 = (unsigned)__cvta_generic_to_shared(&Bs_s[buf][b_kr1][b_nc1]); \
        asm volatile("cp.async.cg.shared.global [%0], [%1], 16, %2;" ::             \
                     "r"(da0), "l"(Asrc0 + (k0)), "r"(sz_a0));                      \
        asm volatile("cp.async.cg.shared.global [%0], [%1], 16, %2;" ::             \
                     "r"(da1), "l"(Asrc1 + (k0)), "r"(sz_a1));                      \
        asm volatile("cp.async.cg.shared.global [%0], [%1], 16;" ::                 \
                     "r"(db0), "l"(Bsrc0 + (size_t)(k0) * 256));                    \
        asm volatile("cp.async.cg.shared.global [%0], [%1], 16;" ::                 \
                     "r"(db1), "l"(Bsrc1 + (size_t)(k0) * 256));                    \
        asm volatile("cp.async.commit_group;");                                     \
    }

    LOAD_STAGE(0, 0)

    for (int t = 0; t < ntiles; t++) {
        int buf = t & 1;
        if (t + 1 < ntiles) {
            LOAD_STAGE((t + 1) & 1, (t + 1) * 32)
            asm volatile("cp.async.wait_group 1;");
        } else {
            asm volatile("cp.async.wait_group 0;");
        }
        __syncthreads();

        #pragma unroll
        for (int ks = 0; ks < 2; ks++) {
            unsigned a[4][4], b[4][2];
            #pragma unroll
            for (int mt = 0; mt < 4; mt++) {
                unsigned addr = (unsigned)__cvta_generic_to_shared(
                    &As_s[buf][warp_m + mt * 16 + lmA_row][ks * 16 + lmA_kh]);
                asm volatile(
                    "ldmatrix.sync.aligned.m8n8.x4.shared.b16 {%0,%1,%2,%3}, [%4];"
                    : "=r"(a[mt][0]), "=r"(a[mt][1]), "=r"(a[mt][2]), "=r"(a[mt][3])
                    : "r"(addr));
            }
            #pragma unroll
            for (int p = 0; p < 2; p++) {
                unsigned addr = (unsigned)__cvta_generic_to_shared(
                    &Bs_s[buf][ks * 16 + lmB_kr][warp_n + p * 16 + lmB_no]);
                unsigned r0, r1, r2, r3;
                asm volatile(
                    "ldmatrix.sync.aligned.m8n8.x4.trans.shared.b16 "
                    "{%0,%1,%2,%3}, [%4];"
                    : "=r"(r0), "=r"(r1), "=r"(r2), "=r"(r3)
                    : "r"(addr));
                b[2 * p][0] = r0; b[2 * p][1] = r1;
                b[2 * p + 1][0] = r2; b[2 * p + 1][1] = r3;
            }
            #pragma unroll
            for (int mt = 0; mt < 4; mt++)
                #pragma unroll
                for (int nt = 0; nt < 4; nt++) {
                    asm volatile(
                        "mma.sync.aligned.m16n8k16.row.col.f32.f16.f16.f32 "
                        "{%0,%1,%2,%3}, {%4,%5,%6,%7}, {%8,%9}, {%0,%1,%2,%3};"
                        : "+f"(c[mt][nt][0]), "+f"(c[mt][nt][1]),
                          "+f"(c[mt][nt][2]), "+f"(c[mt][nt][3])
                        : "r"(a[mt][0]), "r"(a[mt][1]), "r"(a[mt][2]), "r"(a[mt][3]),
                          "r"(b[nt][0]), "r"(b[nt][1]));
                }
        }
        __syncthreads();
    }
    #undef LOAD_STAGE

    #pragma unroll
    for (int mt = 0; mt < 4; mt++) {
        int r0 = bm + warp_m + mt * 16 + gid;
        #pragma unroll
        for (int nt = 0; nt < 4; nt++) {
            int col = bn + warp_n + nt * 8 + 2 * tig;
            float bx = 0.f, by = 0.f;
            if (bias) { bx = bias[col]; by = bias[col + 1]; }
            float x0 = c[mt][nt][0] + bx, y0 = c[mt][nt][1] + by;
            float x1 = c[mt][nt][2] + bx, y1 = c[mt][nt][3] + by;
            if (Cf) {
                if (r0 < M)     *(float2*)(Cf + (size_t)r0 * ldc_f + col) = make_float2(x0, y0);
                if (r0 + 8 < M) *(float2*)(Cf + (size_t)(r0 + 8) * ldc_f + col) = make_float2(x1, y1);
            }
            if (Ch) {
                if (r0 < M)     Ch[(size_t)r0 * ldc_h + (col >> 1)]       = __floats2half2_rn(x0, y0);
                if (r0 + 8 < M) Ch[(size_t)(r0 + 8) * ldc_h + (col >> 1)] = __floats2half2_rn(x1, y1);
            }
        }
    }
}

// ---------------- edge mean (CSR gather) + edge_proj (fp16 out) -------------
__global__ void edgeproj_kernel(const float* __restrict__ eattr,
                                const float* __restrict__ Wep,
                                const float* __restrict__ bep) {
    __shared__ float sW[EDGE_DIM][256];
    __shared__ float snef[16][EDGE_DIM];
    int tid = threadIdx.x;
    for (int i = tid; i < EDGE_DIM * 256; i += 256)
        sW[i >> 8][i & 255] = Wep[i];

    int g = tid >> 4;
    int j = tid & 15;
    int n = blockIdx.x * 16 + g;

    float s = 0.f;
    int deg = 0;
    if (n < NN) {
        int off = g_off[n];
        deg = g_off[n + 1] - off;
        for (int e = 0; e < deg; e++) {
            int eid = g_eid[off + e];
            s += eattr[(size_t)eid * EDGE_DIM + j];
        }
    }
    snef[g][j] = s / fmaxf((float)deg, 1.0f);
    __syncthreads();

    if (n < NN) {
        int c0 = j * 16;
        float acc[16];
        #pragma unroll
        for (int c = 0; c < 16; c++) acc[c] = bep[c0 + c];
        #pragma unroll
        for (int k = 0; k < EDGE_DIM; k++) {
            float v = snef[g][k];
            #pragma unroll
            for (int c = 0; c < 16; c++) acc[c] += v * sW[k][c0 + c];
        }
        __half2* outp = reinterpret_cast<__half2*>(g_xcat_h + (size_t)n * 512 + 256 + c0);
        #pragma unroll
        for (int c = 0; c < 16; c += 2)
            outp[c >> 1] = __floats2half2_rn(acc[c], acc[c + 1]);
    }
}

// ---------------- attention dot products (half2 input) ----------------------
__global__ void attn_dots(const float* __restrict__ as_p,
                          const float* __restrict__ ad_p) {
    int n = blockIdx.x;
    int h = threadIdx.x >> 5;
    int l = threadIdx.x & 31;
    const __half2* row = g_xh_h + (size_t)n * 128 + h * 32;
    float2 x = __half22float2(row[l]);
    int c = 2 * l;
    float s = x.x * as_p[h * CH + c] + x.y * as_p[h * CH + c + 1];
    float d = x.x * ad_p[h * CH + c] + x.y * ad_p[h * CH + c + 1];
    s = wredsum(s);
    d = wredsum(d);
    if (l == 0) {
        g_asrc[n * HEADS + h] = s;
        g_adst[n * HEADS + h] = d;
    }
}

// ---------------- GAT aggregation -> fp16 output -----------------------------
__global__ void gat_aggregate(const float* __restrict__ bias,
                              __half2* __restrict__ out) {
    int n = blockIdx.x;
    int h = threadIdx.x >> 5;
    int l = threadIdx.x & 31;
    int off = g_off[n];
    int deg = g_off[n + 1] - off;
    float adst = g_adst[n * HEADS + h];

    const __half2* xr = g_xh_h + (size_t)n * 128 + h * 32;
    float2 xs = __half22float2(xr[l]);
    float wslf = expf(fminf(lrelu(g_asrc[n * HEADS + h] + adst), 60.f));
    float ds = wslf;
    float a0 = wslf * xs.x;
    float a1 = wslf * xs.y;

    int e = 0;
    for (; e + 1 < deg; e += 2) {
        int s0 = g_csr[off + e];
        int s1 = g_csr[off + e + 1];
        float w0 = expf(fminf(lrelu(g_asrc[s0 * HEADS + h] + adst), 60.f));
        float w1 = expf(fminf(lrelu(g_asrc[s1 * HEADS + h] + adst), 60.f));
        float2 v0 = __half22float2(g_xh_h[(size_t)s0 * 128 + h * 32 + l]);
        float2 v1 = __half22float2(g_xh_h[(size_t)s1 * 128 + h * 32 + l]);
        ds += w0 + w1;
        a0 += w0 * v0.x + w1 * v1.x;
        a1 += w0 * v0.y + w1 * v1.y;
    }
    if (e < deg) {
        int s0 = g_csr[off + e];
        float w0 = expf(fminf(lrelu(g_asrc[s0 * HEADS + h] + adst), 60.f));
        float2 v0 = __half22float2(g_xh_h[(size_t)s0 * 128 + h * 32 + l]);
        ds += w0;
        a0 += w0 * v0.x;
        a1 += w0 * v0.y;
    }

    float inv = 1.0f / ds;
    int c = h * CH + 2 * l;
    float b0 = bias[c], b1 = bias[c + 1];
    out[(size_t)n * 128 + (c >> 1)] =
        __floats2half2_rn(elu(a0 * inv + b0), elu(a1 * inv + b1));
}

// ---------------- launch ----------------------------------------------------
extern "C" void kernel_launch(void* const* d_in, const int* in_sizes, int n_in,
                              void* d_out, int out_size) {
    const float* node_feats = (const float*)d_in[0];
    const float* edge_attr  = (const float*)d_in[1];
    const float* Wnp = (const float*)d_in[2];
    const float* bnp = (const float*)d_in[3];
    const float* Wep = (const float*)d_in[4];
    const float* bep = (const float*)d_in[5];
    const float* Wg1 = (const float*)d_in[6];
    const float* as1 = (const float*)d_in[7];
    const float* ad1 = (const float*)d_in[8];
    const float* bg1 = (const float*)d_in[9];
    const float* Wg2 = (const float*)d_in[10];
    const float* as2 = (const float*)d_in[11];
    const float* ad2 = (const float*)d_in[12];
    const float* bg2 = (const float*)d_in[13];
    const float* Wo  = (const float*)d_in[14];
    const float* bo  = (const float*)d_in[15];
    const int* ei_raw = (const int*)d_in[16];
    float* out = (float*)d_out;

    __half *nfh, *xcath, *wnph, *wg1h, *wg2h, *woh;
    __half2 *xhh, *hh;
    cudaGetSymbolAddress((void**)&nfh,   g_nf_h);
    cudaGetSymbolAddress((void**)&xcath, g_xcat_h);
    cudaGetSymbolAddress((void**)&wnph,  g_wnp_h);
    cudaGetSymbolAddress((void**)&wg1h,  g_wg1_h);
    cudaGetSymbolAddress((void**)&wg2h,  g_wg2_h);
    cudaGetSymbolAddress((void**)&woh,   g_wo_h);
    cudaGetSymbolAddress((void**)&xhh,   g_xh_h);
    cudaGetSymbolAddress((void**)&hh,    g_hh);

    const int EB = (EE + 255) / 256;

    // fp32 -> fp16 conversions (weights + node_feats)
    f2h_kernel<<<(NN * NODE_IN / 2 + 255) / 256, 256>>>(node_feats, (__half2*)nfh, NN * NODE_IN / 2);
    f2h_kernel<<<(NODE_IN * 256 / 2 + 255) / 256, 256>>>(Wnp, (__half2*)wnph, NODE_IN * 256 / 2);
    f2h_kernel<<<(512 * 256 / 2 + 255) / 256, 256>>>(Wg1, (__half2*)wg1h, 512 * 256 / 2);
    f2h_kernel<<<(256 * 256 / 2 + 255) / 256, 256>>>(Wg2, (__half2*)wg2h, 256 * 256 / 2);
    f2h_kernel<<<(256 * 256 / 2 + 255) / 256, 256>>>(Wo, (__half2*)woh, 256 * 256 / 2);

    // graph build
    detect_kernel<<<1, 32>>>(ei_raw);
    zero_cnt<<<NBLK, SCAN_B>>>();
    convert_edges<<<EB, 256>>>(ei_raw);
    scan1<<<NBLK, SCAN_B>>>();
    scan2<<<1, SCAN_B>>>();
    scan3<<<NBLK, SCAN_B>>>();
    edge_fill_csr<<<EB, 256>>>();

    dim3 ggrid(2, (NN + 127) / 128);

    // node_proj -> xcat[:, :256] (fp16)
    gemm_h<<<ggrid, 256>>>(nfh, NODE_IN, wnph, bnp,
                           nullptr, 0, (__half2*)xcath, 256, NN, NODE_IN);
    // edge mean + edge_proj -> xcat[:, 256:512] (fp16)
    edgeproj_kernel<<<(NN + 15) / 16, 256>>>(edge_attr, Wep, bep);

    // ---- GAT layer 1 ----
    gemm_h<<<ggrid, 256>>>(xcath, 512, wg1h, nullptr,
                           nullptr, 0, xhh, 128, NN, 512);
    attn_dots<<<NN, 128>>>(as1, ad1);
    gat_aggregate<<<NN, 128>>>(bg1, hh);

    // ---- GAT layer 2 ----
    gemm_h<<<ggrid, 256>>>((const __half*)hh, 256, wg2h, nullptr,
                           nullptr, 0, xhh, 128, NN, 256);
    attn_dots<<<NN, 128>>>(as2, ad2);
    gat_aggregate<<<NN, 128>>>(bg2, hh);

    // ---- out_proj -> d_out (fp32) ----
    gemm_h<<<ggrid, 256>>>((const __half*)hh, 256, woh, bo,
                           out, 256, nullptr, 0, NN, 256);
}